// round 12
// baseline (speedup 1.0000x reference)
#include <cuda_runtime.h>
#include <math.h>
#include <stdint.h>

// Problem shape (fixed by the reference)
#define BB 16
#define SS 2048
#define EE 512
#define HH 1024
#define NROWS (BB * SS)

// Scratch (allocation-free rule: __device__ globals)
__device__ float g_scores[(size_t)BB * SS * SS];  // 256 MB
__device__ float g_attn  [(size_t)BB * SS * EE];
__device__ float g_x     [(size_t)BB * SS * EE];
__device__ float g_h     [(size_t)BB * SS * HH];
__device__ float g_ff    [(size_t)BB * SS * EE];
__device__ float g_vt    [(size_t)BB * SS * EE];  // V^T per batch [E, S]
__device__ float g_w1t   [(size_t)EE * HH];       // [H, E]
__device__ float g_w2t   [(size_t)EE * HH];       // [E, H]

__device__ __forceinline__ float gelu_exact(float v) {
    return 0.5f * v * (1.0f + erff(v * 0.70710678118654752f));
}

// ============================ PTX helpers (base ISA only) ============================
__device__ __forceinline__ uint32_t smem_u32(const void* p) {
    uint32_t a;
    asm("{ .reg .u64 t; cvta.to.shared.u64 t, %1; cvt.u32.u64 %0, t; }"
        : "=r"(a) : "l"(p));
    return a;
}

__device__ __forceinline__ void cp_async16(uint32_t dst, const void* src) {
    asm volatile("cp.async.cg.shared.global [%0], [%1], 16;"
                 :: "r"(dst), "l"(src) : "memory");
}
__device__ __forceinline__ void cp_commit() {
    asm volatile("cp.async.commit_group;" ::: "memory");
}
template <int N>
__device__ __forceinline__ void cp_wait() {
    asm volatile("cp.async.wait_group %0;" :: "n"(N) : "memory");
}

// ldmatrix x4: four 8x8(16B-row) tiles; for 32-bit data each lane gets one
// 4B element in the (lane>>2, lane&3) mma-fragment pattern.
__device__ __forceinline__ void ldsm_x4(uint32_t* r, uint32_t addr) {
    asm volatile("ldmatrix.sync.aligned.m8n8.x4.shared.b16 {%0,%1,%2,%3}, [%4];"
                 : "=r"(r[0]), "=r"(r[1]), "=r"(r[2]), "=r"(r[3]) : "r"(addr));
}

__device__ __forceinline__ void mma_tf32(float* c, const uint32_t* a, const uint32_t* b) {
    asm volatile(
        "mma.sync.aligned.m16n8k8.row.col.f32.tf32.tf32.f32 "
        "{%0,%1,%2,%3}, {%4,%5,%6,%7}, {%8,%9}, {%0,%1,%2,%3};"
        : "+f"(c[0]), "+f"(c[1]), "+f"(c[2]), "+f"(c[3])
        : "r"(a[0]), "r"(a[1]), "r"(a[2]), "r"(a[3]), "r"(b[0]), "r"(b[1]));
}

// ============================ GEMM kernel ============================
// D = A @ B^T, A [*, K] row-major, B [*, K] row-major (NT).
// CTA tile 128x128, BK=32, 2-stage cp.async pipeline (2 CTAs/SM),
// fragments via ldmatrix.x4, raw fp32 bits into tf32 mma (truncation).
// 8 warps: wm in {0,1} (64 rows each), wn in {0..3} (32 cols each).
// EPI: 0 = alpha*acc, 1 = bias + exact GELU, 2 = bias
#define BK 32
#define ROWPAD 36                  // floats per smem row (bank-spread + 16B aligned)
#define STAGE_F (2 * 128 * ROWPAD) // floats per stage (A+B)
#define GEMM_SMEM (2 * STAGE_F * 4)

template <int EPI>
__global__ __launch_bounds__(256, 2)
void gemm_mma_kernel(const float* __restrict__ A, const float* __restrict__ B,
                     float* __restrict__ C, int ldC, long long cBatch,
                     int aBatchRows, int bBatchRows, int K,
                     const float* __restrict__ bias, float alpha) {
    extern __shared__ float smem[];
    const int tid = threadIdx.x;
    const int bz = blockIdx.z;
    const int mBase = bz * aBatchRows + blockIdx.y * 128;
    const int nBase = bz * bBatchRows + blockIdx.x * 128;

    // loader mapping: each thread copies 4 float4 for A and 4 for B
    const int lr = tid >> 1;               // row 0..127
    const int lq = (tid & 1) * 4;          // float4 index base 0 or 4
    const float* aSrc = A + (long long)(mBase + lr) * K + lq * 4;
    const float* bSrc = B + (long long)(nBase + lr) * K + lq * 4;
    const uint32_t sBase = smem_u32(smem);
    const uint32_t aDst = sBase + (lr * ROWPAD + lq * 4) * 4;
    const uint32_t bDst = aDst + 128 * ROWPAD * 4;

    const int T = K / BK;

    // prologue: stage 0
    #pragma unroll
    for (int i = 0; i < 4; i++) {
        cp_async16(aDst + i * 16, aSrc + i * 4);
        cp_async16(bDst + i * 16, bSrc + i * 4);
    }
    cp_commit();

    const int lane = tid & 31, warp = tid >> 5;
    const int wm = warp & 1, wn = warp >> 1;   // wm: 0..1, wn: 0..3
    const int gid = lane >> 2, tq = lane & 3;

    // ldmatrix per-lane address offsets (bytes, within a stage)
    const int lm = lane >> 3, lrw = lane & 7;  // matrix id 0..3, row 0..7
    // A x4 (step i): m0=rows+0 col k0 | m1=rows+8 col k0 | m2=rows+0 col k0+4 | m3=rows+8 col k0+4
    const uint32_t aOff = ((wm * 64 + (lm & 1) * 8 + lrw) * ROWPAD + (lm >> 1) * 4) * 4;
    // B x4 (pair p -> j=2p,2p+1): m0=j col k0 | m1=j col k0+4 | m2=j+1 col k0 | m3=j+1 col k0+4
    const uint32_t bOff = 128 * ROWPAD * 4 +
                          ((wn * 32 + (lm >> 1) * 8 + lrw) * ROWPAD + (lm & 1) * 4) * 4;

    float acc[4][4][4];
    #pragma unroll
    for (int i = 0; i < 4; i++)
        #pragma unroll
        for (int j = 0; j < 4; j++)
            #pragma unroll
            for (int r = 0; r < 4; r++) acc[i][j][r] = 0.0f;

    for (int t = 0; t < T; t++) {
        // issue loads for t+1 into the other buffer (prior contents consumed
        // at t-1; end-of-iteration __syncthreads guarantees safety)
        if (t + 1 < T) {
            const uint32_t so = ((t + 1) & 1) * STAGE_F * 4;
            const int kt = (t + 1) * BK;
            #pragma unroll
            for (int i = 0; i < 4; i++) {
                cp_async16(aDst + so + i * 16, aSrc + kt + i * 4);
                cp_async16(bDst + so + i * 16, bSrc + kt + i * 4);
            }
        }
        cp_commit();          // always commit (empty group on last iter)
        cp_wait<1>();         // stage t complete; stage t+1 in flight
        __syncthreads();

        const uint32_t stBase = sBase + (t & 1) * STAGE_F * 4;

        #pragma unroll
        for (int ks = 0; ks < 4; ks++) {
            const uint32_t k0b = ks * 32;          // 8 floats = 32 bytes
            uint32_t af[4][4], bf[4][2];
            #pragma unroll
            for (int i = 0; i < 4; i++)
                ldsm_x4(af[i], stBase + aOff + k0b + i * (16 * ROWPAD * 4));
            #pragma unroll
            for (int p = 0; p < 2; p++) {
                uint32_t tmp[4];
                ldsm_x4(tmp, stBase + bOff + k0b + p * (16 * ROWPAD * 4));
                bf[2 * p][0]     = tmp[0];
                bf[2 * p][1]     = tmp[1];
                bf[2 * p + 1][0] = tmp[2];
                bf[2 * p + 1][1] = tmp[3];
            }
            #pragma unroll
            for (int i = 0; i < 4; i++)
                #pragma unroll
                for (int j = 0; j < 4; j++)
                    mma_tf32(acc[i][j], af[i], bf[j]);
        }
        __syncthreads();
    }

    // epilogue
    float* Cb = C + (long long)bz * cBatch;
    float2 bv[4];
    if (EPI != 0) {
        #pragma unroll
        for (int j = 0; j < 4; j++)
            bv[j] = *(const float2*)(bias + blockIdx.x * 128 + wn * 32 + j * 8 + 2 * tq);
    }
    #pragma unroll
    for (int i = 0; i < 4; i++) {
        const int row = blockIdx.y * 128 + wm * 64 + i * 16 + gid;
        #pragma unroll
        for (int j = 0; j < 4; j++) {
            const int col = blockIdx.x * 128 + wn * 32 + j * 8 + 2 * tq;
            float v0 = acc[i][j][0], v1 = acc[i][j][1];
            float v2 = acc[i][j][2], v3 = acc[i][j][3];
            if (EPI == 0) {
                v0 *= alpha; v1 *= alpha; v2 *= alpha; v3 *= alpha;
            } else if (EPI == 1) {
                v0 = gelu_exact(v0 + bv[j].x); v1 = gelu_exact(v1 + bv[j].y);
                v2 = gelu_exact(v2 + bv[j].x); v3 = gelu_exact(v3 + bv[j].y);
            } else {
                v0 += bv[j].x; v1 += bv[j].y;
                v2 += bv[j].x; v3 += bv[j].y;
            }
            *(float2*)(Cb + (long long)row * ldC + col)       = make_float2(v0, v1);
            *(float2*)(Cb + (long long)(row + 8) * ldC + col) = make_float2(v2, v3);
        }
    }
}

// ============================ transpose ============================
__global__ __launch_bounds__(256)
void transpose_kernel(const float* __restrict__ in, float* __restrict__ out,
                      int rows, int cols) {
    __shared__ float t[32][33];
    const long long boff = (long long)blockIdx.z * rows * cols;
    in += boff; out += boff;
    const int c0 = blockIdx.x * 32, r0 = blockIdx.y * 32;
    const int tx = threadIdx.x & 31, ty = threadIdx.x >> 5;  // 32 x 8
    #pragma unroll
    for (int i = 0; i < 4; i++)
        t[ty + 8 * i][tx] = in[(long long)(r0 + ty + 8 * i) * cols + c0 + tx];
    __syncthreads();
    #pragma unroll
    for (int i = 0; i < 4; i++)
        out[(long long)(c0 + ty + 8 * i) * rows + r0 + tx] = t[tx][ty + 8 * i];
}

// ============================ softmax ============================
__global__ __launch_bounds__(256)
void softmax_kernel(float* __restrict__ P) {
    float* row = P + (size_t)blockIdx.x * 2048;
    const int tid = threadIdx.x;

    float4 v0 = ((float4*)row)[tid];
    float4 v1 = ((float4*)row)[tid + 256];

    float m = fmaxf(fmaxf(fmaxf(v0.x, v0.y), fmaxf(v0.z, v0.w)),
                    fmaxf(fmaxf(v1.x, v1.y), fmaxf(v1.z, v1.w)));

    __shared__ float smax[8];
    __shared__ float ssum[8];
    const int wid = tid >> 5, lane = tid & 31;

    #pragma unroll
    for (int o = 16; o > 0; o >>= 1)
        m = fmaxf(m, __shfl_xor_sync(0xffffffffu, m, o));
    if (lane == 0) smax[wid] = m;
    __syncthreads();
    m = smax[0];
    #pragma unroll
    for (int i = 1; i < 8; i++) m = fmaxf(m, smax[i]);

    v0.x = __expf(v0.x - m); v0.y = __expf(v0.y - m);
    v0.z = __expf(v0.z - m); v0.w = __expf(v0.w - m);
    v1.x = __expf(v1.x - m); v1.y = __expf(v1.y - m);
    v1.z = __expf(v1.z - m); v1.w = __expf(v1.w - m);

    float s = v0.x + v0.y + v0.z + v0.w + v1.x + v1.y + v1.z + v1.w;
    #pragma unroll
    for (int o = 16; o > 0; o >>= 1)
        s += __shfl_xor_sync(0xffffffffu, s, o);
    if (lane == 0) ssum[wid] = s;
    __syncthreads();
    s = ssum[0];
    #pragma unroll
    for (int i = 1; i < 8; i++) s += ssum[i];

    const float inv = 1.0f / s;
    v0.x *= inv; v0.y *= inv; v0.z *= inv; v0.w *= inv;
    v1.x *= inv; v1.y *= inv; v1.z *= inv; v1.w *= inv;

    ((float4*)row)[tid]       = v0;
    ((float4*)row)[tid + 256] = v1;
}

// ============================ add + LayerNorm ============================
__global__ __launch_bounds__(128)
void add_ln_kernel(const float* __restrict__ A, const float* __restrict__ Bv,
                   const float* __restrict__ gamma, const float* __restrict__ beta,
                   float* __restrict__ out) {
    const size_t base = (size_t)blockIdx.x * 512;
    const int tid = threadIdx.x;

    float4 a = ((const float4*)(A + base))[tid];
    float4 b = ((const float4*)(Bv + base))[tid];
    float v0 = a.x + b.x, v1 = a.y + b.y, v2 = a.z + b.z, v3 = a.w + b.w;

    float s  = v0 + v1 + v2 + v3;
    float sq = v0 * v0 + v1 * v1 + v2 * v2 + v3 * v3;

    __shared__ float ss[4];
    __shared__ float sk[4];
    const int wid = tid >> 5, lane = tid & 31;
    #pragma unroll
    for (int o = 16; o > 0; o >>= 1) {
        s  += __shfl_xor_sync(0xffffffffu, s, o);
        sq += __shfl_xor_sync(0xffffffffu, sq, o);
    }
    if (lane == 0) { ss[wid] = s; sk[wid] = sq; }
    __syncthreads();
    s  = ss[0] + ss[1] + ss[2] + ss[3];
    sq = sk[0] + sk[1] + sk[2] + sk[3];

    const float mu  = s * (1.0f / 512.0f);
    const float var = sq * (1.0f / 512.0f) - mu * mu;
    const float rs  = rsqrtf(var + 1e-5f);

    float4 g  = ((const float4*)gamma)[tid];
    float4 be = ((const float4*)beta)[tid];

    float4 o;
    o.x = (v0 - mu) * rs * g.x + be.x;
    o.y = (v1 - mu) * rs * g.y + be.y;
    o.z = (v2 - mu) * rs * g.z + be.z;
    o.w = (v3 - mu) * rs * g.w + be.w;
    ((float4*)(out + base))[tid] = o;
}

// ============================ host ============================
extern "C" void kernel_launch(void* const* d_in, const int* in_sizes, int n_in,
                              void* d_out, int out_size) {
    const float* q     = (const float*)d_in[0];
    const float* k     = (const float*)d_in[1];
    const float* v     = (const float*)d_in[2];
    const float* ln1_g = (const float*)d_in[3];
    const float* ln1_b = (const float*)d_in[4];
    const float* w1    = (const float*)d_in[5];
    const float* b1    = (const float*)d_in[6];
    const float* w2    = (const float*)d_in[7];
    const float* b2    = (const float*)d_in[8];
    const float* ln3_g = (const float*)d_in[9];
    const float* ln3_b = (const float*)d_in[10];
    float* out = (float*)d_out;

    float *scores, *attn, *x, *h, *ff, *vt, *w1t, *w2t;
    cudaGetSymbolAddress((void**)&scores, g_scores);
    cudaGetSymbolAddress((void**)&attn,   g_attn);
    cudaGetSymbolAddress((void**)&x,      g_x);
    cudaGetSymbolAddress((void**)&h,      g_h);
    cudaGetSymbolAddress((void**)&ff,     g_ff);
    cudaGetSymbolAddress((void**)&vt,     g_vt);
    cudaGetSymbolAddress((void**)&w1t,    g_w1t);
    cudaGetSymbolAddress((void**)&w2t,    g_w2t);

    cudaFuncSetAttribute(gemm_mma_kernel<0>,
                         cudaFuncAttributeMaxDynamicSharedMemorySize, GEMM_SMEM);
    cudaFuncSetAttribute(gemm_mma_kernel<1>,
                         cudaFuncAttributeMaxDynamicSharedMemorySize, GEMM_SMEM);
    cudaFuncSetAttribute(gemm_mma_kernel<2>,
                         cudaFuncAttributeMaxDynamicSharedMemorySize, GEMM_SMEM);

    const float alpha = 1.0f / sqrtf((float)EE);

    // 0) transposes: V -> Vt (per batch), w1 -> w1t, w2 -> w2t
    transpose_kernel<<<dim3(EE / 32, SS / 32, BB), 256>>>(v, vt, SS, EE);
    transpose_kernel<<<dim3(HH / 32, EE / 32, 1), 256>>>(w1, w1t, EE, HH);
    transpose_kernel<<<dim3(EE / 32, HH / 32, 1), 256>>>(w2, w2t, HH, EE);

    // 1) scores = alpha * q @ k^T   [per batch 2048x2048, K=512]
    gemm_mma_kernel<0><<<dim3(SS / 128, SS / 128, BB), 256, GEMM_SMEM>>>(
        q, k, scores, SS, (long long)SS * SS, SS, SS, EE, nullptr, alpha);

    // 2) softmax rows
    softmax_kernel<<<NROWS, 256>>>(scores);

    // 3) attn = P @ Vt^T            [per batch 2048x512, K=2048]
    gemm_mma_kernel<0><<<dim3(EE / 128, SS / 128, BB), 256, GEMM_SMEM>>>(
        scores, vt, attn, EE, (long long)SS * EE, SS, EE, SS, nullptr, 1.0f);

    // 4) x = LN(q + attn)
    add_ln_kernel<<<NROWS, 128>>>(q, attn, ln1_g, ln1_b, x);

    // 5) h = gelu(x @ w1t^T + b1)   [32768x1024, K=512]
    gemm_mma_kernel<1><<<dim3(HH / 128, NROWS / 128, 1), 256, GEMM_SMEM>>>(
        x, w1t, h, HH, 0LL, 0, 0, EE, b1, 1.0f);

    // 6) ff = h @ w2t^T + b2        [32768x512, K=1024]
    gemm_mma_kernel<2><<<dim3(EE / 128, NROWS / 128, 1), 256, GEMM_SMEM>>>(
        h, w2t, ff, EE, 0LL, 0, 0, HH, b2, 1.0f);

    // 7) out = LN(x + ff)
    add_ln_kernel<<<NROWS, 128>>>(x, ff, ln3_g, ln3_b, out);
}

// round 14
// speedup vs baseline: 1.3251x; 1.3251x over previous
#include <cuda_runtime.h>
#include <math.h>
#include <stdint.h>

// Problem shape (fixed by the reference)
#define BB 16
#define SS 2048
#define EE 512
#define HH 1024
#define NROWS (BB * SS)

// Scratch (allocation-free rule: __device__ globals)
__device__ float g_scores[(size_t)BB * SS * SS];  // 256 MB
__device__ float g_attn  [(size_t)BB * SS * EE];
__device__ float g_x     [(size_t)BB * SS * EE];
__device__ float g_h     [(size_t)BB * SS * HH];
__device__ float g_ff    [(size_t)BB * SS * EE];
__device__ float g_vt    [(size_t)BB * SS * EE];  // V^T per batch [E, S]
__device__ float g_w1t   [(size_t)EE * HH];       // [H, E]
__device__ float g_w2t   [(size_t)EE * HH];       // [E, H]

__device__ __forceinline__ float gelu_exact(float v) {
    return 0.5f * v * (1.0f + erff(v * 0.70710678118654752f));
}

// ============================ PTX helpers (base ISA only) ============================
__device__ __forceinline__ uint32_t smem_u32(const void* p) {
    uint32_t a;
    asm("{ .reg .u64 t; cvta.to.shared.u64 t, %1; cvt.u32.u64 %0, t; }"
        : "=r"(a) : "l"(p));
    return a;
}

__device__ __forceinline__ void cp_async16(uint32_t dst, const void* src) {
    asm volatile("cp.async.cg.shared.global [%0], [%1], 16;"
                 :: "r"(dst), "l"(src) : "memory");
}
__device__ __forceinline__ void cp_commit() {
    asm volatile("cp.async.commit_group;" ::: "memory");
}
template <int N>
__device__ __forceinline__ void cp_wait() {
    asm volatile("cp.async.wait_group %0;" :: "n"(N) : "memory");
}

__device__ __forceinline__ uint32_t f2tf(float f) {
    uint32_t u;
    asm("cvt.rna.tf32.f32 %0, %1;" : "=r"(u) : "f"(f));
    return u;
}

__device__ __forceinline__ void mma_tf32(float* c, const uint32_t* a, const uint32_t* b) {
    asm volatile(
        "mma.sync.aligned.m16n8k8.row.col.f32.tf32.tf32.f32 "
        "{%0,%1,%2,%3}, {%4,%5,%6,%7}, {%8,%9}, {%0,%1,%2,%3};"
        : "+f"(c[0]), "+f"(c[1]), "+f"(c[2]), "+f"(c[3])
        : "r"(a[0]), "r"(a[1]), "r"(a[2]), "r"(a[3]), "r"(b[0]), "r"(b[1]));
}

// ============================ GEMM kernel ============================
// D = A @ B^T, A [*, K] row-major, B [*, K] row-major (NT).
// CTA tile 128x128, BK=32, 2-stage cp.async pipeline (2 CTAs/SM).
// 8 warps: wm in {0,1} (64 rows), wn in {0..3} (32 cols). Per k-step:
// bf loaded just-in-time, af double-buffered across k-steps so the 16-LDS
// A burst overlaps the previous step's 16 MMAs (breaks the post-sync convoy).
// EPI: 0 = alpha*acc, 1 = bias + exact GELU, 2 = bias
#define BK 32
#define ROWPAD 36                  // floats per smem row (bank-spread + 16B aligned)
#define STAGE_F (2 * 128 * ROWPAD) // floats per stage (A+B)
#define GEMM_SMEM (2 * STAGE_F * 4)

template <int EPI>
__global__ __launch_bounds__(256, 2)
void gemm_mma_kernel(const float* __restrict__ A, const float* __restrict__ B,
                     float* __restrict__ C, int ldC, long long cBatch,
                     int aBatchRows, int bBatchRows, int K,
                     const float* __restrict__ bias, float alpha) {
    extern __shared__ float smem[];
    const int tid = threadIdx.x;
    const int bz = blockIdx.z;
    const int mBase = bz * aBatchRows + blockIdx.y * 128;
    const int nBase = bz * bBatchRows + blockIdx.x * 128;

    // loader mapping: each thread copies 4 float4 for A and 4 for B
    const int lr = tid >> 1;               // row 0..127
    const int lq = (tid & 1) * 4;          // float4 index base 0 or 4
    const float* aSrc = A + (long long)(mBase + lr) * K + lq * 4;
    const float* bSrc = B + (long long)(nBase + lr) * K + lq * 4;
    const uint32_t sBase = smem_u32(smem);
    const uint32_t aDst = sBase + (lr * ROWPAD + lq * 4) * 4;
    const uint32_t bDst = aDst + 128 * ROWPAD * 4;

    const int T = K / BK;

    // prologue: stage 0
    #pragma unroll
    for (int i = 0; i < 4; i++) {
        cp_async16(aDst + i * 16, aSrc + i * 4);
        cp_async16(bDst + i * 16, bSrc + i * 4);
    }
    cp_commit();

    const int lane = tid & 31, warp = tid >> 5;
    const int wm = warp & 1, wn = warp >> 1;   // wm: 0..1, wn: 0..3
    const int gid = lane >> 2, tq = lane & 3;

    float acc[4][4][4];
    #pragma unroll
    for (int i = 0; i < 4; i++)
        #pragma unroll
        for (int j = 0; j < 4; j++)
            #pragma unroll
            for (int r = 0; r < 4; r++) acc[i][j][r] = 0.0f;

    uint32_t af[2][4][4];   // A fragments, double-buffered across k-steps

    for (int t = 0; t < T; t++) {
        // issue loads for t+1 into the other buffer (its prior contents were
        // consumed at t-1; end-of-iteration __syncthreads guarantees safety)
        if (t + 1 < T) {
            const uint32_t so = ((t + 1) & 1) * STAGE_F * 4;
            const int kt = (t + 1) * BK;
            #pragma unroll
            for (int i = 0; i < 4; i++) {
                cp_async16(aDst + so + i * 16, aSrc + kt + i * 4);
                cp_async16(bDst + so + i * 16, bSrc + kt + i * 4);
            }
        }
        cp_commit();          // always commit (empty group on last iter)
        cp_wait<1>();         // stage t complete; stage t+1 in flight
        __syncthreads();

        const float* sA = smem + (t & 1) * STAGE_F;
        const float* sB = sA + 128 * ROWPAD;
        const float* pA = sA + (wm * 64 + gid) * ROWPAD + tq;
        const float* pB = sB + (wn * 32 + gid) * ROWPAD + tq;

        // preload A fragments for k-step 0
        #pragma unroll
        for (int i = 0; i < 4; i++) {
            const float* pa = pA + i * 16 * ROWPAD;
            af[0][i][0] = f2tf(pa[0]);
            af[0][i][1] = f2tf(pa[8 * ROWPAD]);
            af[0][i][2] = f2tf(pa[4]);
            af[0][i][3] = f2tf(pa[8 * ROWPAD + 4]);
        }

        #pragma unroll
        for (int ks = 0; ks < 4; ks++) {
            const int cur = ks & 1, nxt = cur ^ 1;
            const int k0 = ks * 8;
            // B fragments for this k-step (issued first; latency covered by
            // the A-prefetch issue stream below)
            uint32_t bf[4][2];
            #pragma unroll
            for (int j = 0; j < 4; j++) {
                const float* pb = pB + j * 8 * ROWPAD + k0;
                bf[j][0] = f2tf(pb[0]);
                bf[j][1] = f2tf(pb[4]);
            }
            // A fragments for NEXT k-step — overlap with this step's MMAs
            if (ks < 3) {
                const int k1 = k0 + 8;
                #pragma unroll
                for (int i = 0; i < 4; i++) {
                    const float* pa = pA + i * 16 * ROWPAD + k1;
                    af[nxt][i][0] = f2tf(pa[0]);
                    af[nxt][i][1] = f2tf(pa[8 * ROWPAD]);
                    af[nxt][i][2] = f2tf(pa[4]);
                    af[nxt][i][3] = f2tf(pa[8 * ROWPAD + 4]);
                }
            }
            #pragma unroll
            for (int i = 0; i < 4; i++)
                #pragma unroll
                for (int j = 0; j < 4; j++)
                    mma_tf32(acc[i][j], af[cur][i], bf[j]);
        }
        __syncthreads();
    }

    // epilogue
    float* Cb = C + (long long)bz * cBatch;
    float2 bv[4];
    if (EPI != 0) {
        #pragma unroll
        for (int j = 0; j < 4; j++)
            bv[j] = *(const float2*)(bias + blockIdx.x * 128 + wn * 32 + j * 8 + 2 * tq);
    }
    #pragma unroll
    for (int i = 0; i < 4; i++) {
        const int row = blockIdx.y * 128 + wm * 64 + i * 16 + gid;
        #pragma unroll
        for (int j = 0; j < 4; j++) {
            const int col = blockIdx.x * 128 + wn * 32 + j * 8 + 2 * tq;
            float v0 = acc[i][j][0], v1 = acc[i][j][1];
            float v2 = acc[i][j][2], v3 = acc[i][j][3];
            if (EPI == 0) {
                v0 *= alpha; v1 *= alpha; v2 *= alpha; v3 *= alpha;
            } else if (EPI == 1) {
                v0 = gelu_exact(v0 + bv[j].x); v1 = gelu_exact(v1 + bv[j].y);
                v2 = gelu_exact(v2 + bv[j].x); v3 = gelu_exact(v3 + bv[j].y);
            } else {
                v0 += bv[j].x; v1 += bv[j].y;
                v2 += bv[j].x; v3 += bv[j].y;
            }
            *(float2*)(Cb + (long long)row * ldC + col)       = make_float2(v0, v1);
            *(float2*)(Cb + (long long)(row + 8) * ldC + col) = make_float2(v2, v3);
        }
    }
}

// ============================ transpose ============================
__global__ __launch_bounds__(256)
void transpose_kernel(const float* __restrict__ in, float* __restrict__ out,
                      int rows, int cols) {
    __shared__ float t[32][33];
    const long long boff = (long long)blockIdx.z * rows * cols;
    in += boff; out += boff;
    const int c0 = blockIdx.x * 32, r0 = blockIdx.y * 32;
    const int tx = threadIdx.x & 31, ty = threadIdx.x >> 5;  // 32 x 8
    #pragma unroll
    for (int i = 0; i < 4; i++)
        t[ty + 8 * i][tx] = in[(long long)(r0 + ty + 8 * i) * cols + c0 + tx];
    __syncthreads();
    #pragma unroll
    for (int i = 0; i < 4; i++)
        out[(long long)(c0 + ty + 8 * i) * rows + r0 + tx] = t[tx][ty + 8 * i];
}

// ============================ softmax ============================
__global__ __launch_bounds__(256)
void softmax_kernel(float* __restrict__ P) {
    float* row = P + (size_t)blockIdx.x * 2048;
    const int tid = threadIdx.x;

    float4 v0 = ((float4*)row)[tid];
    float4 v1 = ((float4*)row)[tid + 256];

    float m = fmaxf(fmaxf(fmaxf(v0.x, v0.y), fmaxf(v0.z, v0.w)),
                    fmaxf(fmaxf(v1.x, v1.y), fmaxf(v1.z, v1.w)));

    __shared__ float smax[8];
    __shared__ float ssum[8];
    const int wid = tid >> 5, lane = tid & 31;

    #pragma unroll
    for (int o = 16; o > 0; o >>= 1)
        m = fmaxf(m, __shfl_xor_sync(0xffffffffu, m, o));
    if (lane == 0) smax[wid] = m;
    __syncthreads();
    m = smax[0];
    #pragma unroll
    for (int i = 1; i < 8; i++) m = fmaxf(m, smax[i]);

    v0.x = __expf(v0.x - m); v0.y = __expf(v0.y - m);
    v0.z = __expf(v0.z - m); v0.w = __expf(v0.w - m);
    v1.x = __expf(v1.x - m); v1.y = __expf(v1.y - m);
    v1.z = __expf(v1.z - m); v1.w = __expf(v1.w - m);

    float s = v0.x + v0.y + v0.z + v0.w + v1.x + v1.y + v1.z + v1.w;
    #pragma unroll
    for (int o = 16; o > 0; o >>= 1)
        s += __shfl_xor_sync(0xffffffffu, s, o);
    if (lane == 0) ssum[wid] = s;
    __syncthreads();
    s = ssum[0];
    #pragma unroll
    for (int i = 1; i < 8; i++) s += ssum[i];

    const float inv = 1.0f / s;
    v0.x *= inv; v0.y *= inv; v0.z *= inv; v0.w *= inv;
    v1.x *= inv; v1.y *= inv; v1.z *= inv; v1.w *= inv;

    ((float4*)row)[tid]       = v0;
    ((float4*)row)[tid + 256] = v1;
}

// ============================ add + LayerNorm ============================
__global__ __launch_bounds__(128)
void add_ln_kernel(const float* __restrict__ A, const float* __restrict__ Bv,
                   const float* __restrict__ gamma, const float* __restrict__ beta,
                   float* __restrict__ out) {
    const size_t base = (size_t)blockIdx.x * 512;
    const int tid = threadIdx.x;

    float4 a = ((const float4*)(A + base))[tid];
    float4 b = ((const float4*)(Bv + base))[tid];
    float v0 = a.x + b.x, v1 = a.y + b.y, v2 = a.z + b.z, v3 = a.w + b.w;

    float s  = v0 + v1 + v2 + v3;
    float sq = v0 * v0 + v1 * v1 + v2 * v2 + v3 * v3;

    __shared__ float ss[4];
    __shared__ float sk[4];
    const int wid = tid >> 5, lane = tid & 31;
    #pragma unroll
    for (int o = 16; o > 0; o >>= 1) {
        s  += __shfl_xor_sync(0xffffffffu, s, o);
        sq += __shfl_xor_sync(0xffffffffu, sq, o);
    }
    if (lane == 0) { ss[wid] = s; sk[wid] = sq; }
    __syncthreads();
    s  = ss[0] + ss[1] + ss[2] + ss[3];
    sq = sk[0] + sk[1] + sk[2] + sk[3];

    const float mu  = s * (1.0f / 512.0f);
    const float var = sq * (1.0f / 512.0f) - mu * mu;
    const float rs  = rsqrtf(var + 1e-5f);

    float4 g  = ((const float4*)gamma)[tid];
    float4 be = ((const float4*)beta)[tid];

    float4 o;
    o.x = (v0 - mu) * rs * g.x + be.x;
    o.y = (v1 - mu) * rs * g.y + be.y;
    o.z = (v2 - mu) * rs * g.z + be.z;
    o.w = (v3 - mu) * rs * g.w + be.w;
    ((float4*)(out + base))[tid] = o;
}

// ============================ host ============================
extern "C" void kernel_launch(void* const* d_in, const int* in_sizes, int n_in,
                              void* d_out, int out_size) {
    const float* q     = (const float*)d_in[0];
    const float* k     = (const float*)d_in[1];
    const float* v     = (const float*)d_in[2];
    const float* ln1_g = (const float*)d_in[3];
    const float* ln1_b = (const float*)d_in[4];
    const float* w1    = (const float*)d_in[5];
    const float* b1    = (const float*)d_in[6];
    const float* w2    = (const float*)d_in[7];
    const float* b2    = (const float*)d_in[8];
    const float* ln3_g = (const float*)d_in[9];
    const float* ln3_b = (const float*)d_in[10];
    float* out = (float*)d_out;

    float *scores, *attn, *x, *h, *ff, *vt, *w1t, *w2t;
    cudaGetSymbolAddress((void**)&scores, g_scores);
    cudaGetSymbolAddress((void**)&attn,   g_attn);
    cudaGetSymbolAddress((void**)&x,      g_x);
    cudaGetSymbolAddress((void**)&h,      g_h);
    cudaGetSymbolAddress((void**)&ff,     g_ff);
    cudaGetSymbolAddress((void**)&vt,     g_vt);
    cudaGetSymbolAddress((void**)&w1t,    g_w1t);
    cudaGetSymbolAddress((void**)&w2t,    g_w2t);

    cudaFuncSetAttribute(gemm_mma_kernel<0>,
                         cudaFuncAttributeMaxDynamicSharedMemorySize, GEMM_SMEM);
    cudaFuncSetAttribute(gemm_mma_kernel<1>,
                         cudaFuncAttributeMaxDynamicSharedMemorySize, GEMM_SMEM);
    cudaFuncSetAttribute(gemm_mma_kernel<2>,
                         cudaFuncAttributeMaxDynamicSharedMemorySize, GEMM_SMEM);

    const float alpha = 1.0f / sqrtf((float)EE);

    // 0) transposes: V -> Vt (per batch), w1 -> w1t, w2 -> w2t
    transpose_kernel<<<dim3(EE / 32, SS / 32, BB), 256>>>(v, vt, SS, EE);
    transpose_kernel<<<dim3(HH / 32, EE / 32, 1), 256>>>(w1, w1t, EE, HH);
    transpose_kernel<<<dim3(EE / 32, HH / 32, 1), 256>>>(w2, w2t, HH, EE);

    // 1) scores = alpha * q @ k^T   [per batch 2048x2048, K=512]
    gemm_mma_kernel<0><<<dim3(SS / 128, SS / 128, BB), 256, GEMM_SMEM>>>(
        q, k, scores, SS, (long long)SS * SS, SS, SS, EE, nullptr, alpha);

    // 2) softmax rows
    softmax_kernel<<<NROWS, 256>>>(scores);

    // 3) attn = P @ Vt^T            [per batch 2048x512, K=2048]
    gemm_mma_kernel<0><<<dim3(EE / 128, SS / 128, BB), 256, GEMM_SMEM>>>(
        scores, vt, attn, EE, (long long)SS * EE, SS, EE, SS, nullptr, 1.0f);

    // 4) x = LN(q + attn)
    add_ln_kernel<<<NROWS, 128>>>(q, attn, ln1_g, ln1_b, x);

    // 5) h = gelu(x @ w1t^T + b1)   [32768x1024, K=512]
    gemm_mma_kernel<1><<<dim3(HH / 128, NROWS / 128, 1), 256, GEMM_SMEM>>>(
        x, w1t, h, HH, 0LL, 0, 0, EE, b1, 1.0f);

    // 6) ff = h @ w2t^T + b2        [32768x512, K=1024]
    gemm_mma_kernel<2><<<dim3(EE / 128, NROWS / 128, 1), 256, GEMM_SMEM>>>(
        h, w2t, ff, EE, 0LL, 0, 0, HH, b2, 1.0f);

    // 7) out = LN(x + ff)
    add_ln_kernel<<<NROWS, 128>>>(x, ff, ln3_g, ln3_b, out);
}

// round 15
// speedup vs baseline: 2.5221x; 1.9033x over previous
#include <cuda_runtime.h>
#include <cuda_fp16.h>
#include <math.h>
#include <stdint.h>

// Problem shape (fixed by the reference)
#define BB 16
#define SS 2048
#define EE 512
#define HH 1024
#define NROWS (BB * SS)

// Scratch (allocation-free rule: __device__ globals)
__device__ float  g_scores[(size_t)BB * SS * SS];  // 256 MB (QK^T, f32)
__device__ __half g_ph    [(size_t)BB * SS * SS];  // 128 MB (softmax(P), f16)
__device__ float  g_attn  [(size_t)BB * SS * EE];
__device__ float  g_x     [(size_t)BB * SS * EE];
__device__ __half g_xh    [(size_t)BB * SS * EE];
__device__ __half g_hh    [(size_t)BB * SS * HH];  // gelu output, f16
__device__ float  g_ff    [(size_t)BB * SS * EE];
__device__ __half g_qh    [(size_t)BB * SS * EE];
__device__ __half g_kh    [(size_t)BB * SS * EE];
__device__ __half g_vth   [(size_t)BB * SS * EE];  // V^T per batch [E, S]
__device__ __half g_w1th  [(size_t)EE * HH];       // [H, E]
__device__ __half g_w2th  [(size_t)EE * HH];       // [E, H]

__device__ __forceinline__ float gelu_exact(float v) {
    return 0.5f * v * (1.0f + erff(v * 0.70710678118654752f));
}

// ============================ PTX helpers (base ISA only) ============================
__device__ __forceinline__ uint32_t smem_u32(const void* p) {
    uint32_t a;
    asm("{ .reg .u64 t; cvta.to.shared.u64 t, %1; cvt.u32.u64 %0, t; }"
        : "=r"(a) : "l"(p));
    return a;
}

__device__ __forceinline__ void cp_async16(uint32_t dst, const void* src) {
    asm volatile("cp.async.cg.shared.global [%0], [%1], 16;"
                 :: "r"(dst), "l"(src) : "memory");
}
__device__ __forceinline__ void cp_commit() {
    asm volatile("cp.async.commit_group;" ::: "memory");
}
template <int N>
__device__ __forceinline__ void cp_wait() {
    asm volatile("cp.async.wait_group %0;" :: "n"(N) : "memory");
}

// fp16 MMA, fp32 accumulate: D[16x8] += A[16x16] * B[8x16]^T
__device__ __forceinline__ void mma_f16(float* c, const uint32_t* a, const uint32_t* b) {
    asm volatile(
        "mma.sync.aligned.m16n8k16.row.col.f32.f16.f16.f32 "
        "{%0,%1,%2,%3}, {%4,%5,%6,%7}, {%8,%9}, {%0,%1,%2,%3};"
        : "+f"(c[0]), "+f"(c[1]), "+f"(c[2]), "+f"(c[3])
        : "r"(a[0]), "r"(a[1]), "r"(a[2]), "r"(a[3]), "r"(b[0]), "r"(b[1]));
}

// ============================ GEMM kernel ============================
// D = A @ B^T, A [*, K] row-major f16, B [*, K] row-major f16 (NT).
// CTA tile 128x128, BK=32 (halves), 2-stage cp.async pipeline (2 CTAs/SM).
// 8 warps: wm in {0,1} (64 rows), wn in {0..3} (32 cols); 2 k16-steps/chunk.
// EPI: 0 = alpha*acc -> f32, 1 = bias + exact GELU -> f16, 2 = bias -> f32
#define BK 32                    // halves per K chunk
#define RP 40                    // halves per smem row (80B: conflict-free, 16B-aligned)
#define STAGE_H (2 * 128 * RP)   // halves per stage (A+B) = 20KB
#define GEMM_SMEM (2 * STAGE_H * 2)

template <int EPI>
__global__ __launch_bounds__(256, 2)
void gemm_mma_kernel(const __half* __restrict__ A, const __half* __restrict__ B,
                     void* __restrict__ Cv, int ldC, long long cBatch,
                     int aBatchRows, int bBatchRows, int K,
                     const float* __restrict__ bias, float alpha) {
    extern __shared__ __half smem[];
    const int tid = threadIdx.x;
    const int bz = blockIdx.z;
    const int mBase = bz * aBatchRows + blockIdx.y * 128;
    const int nBase = bz * bBatchRows + blockIdx.x * 128;

    // loader: each thread copies 2x16B for A and 2x16B for B
    const int lr = tid >> 1;            // row 0..127
    const int lq = (tid & 1) * 16;      // half offset within 32-half row
    const __half* aSrc = A + (long long)(mBase + lr) * K + lq;
    const __half* bSrc = B + (long long)(nBase + lr) * K + lq;
    const uint32_t sBase = smem_u32(smem);
    const uint32_t aDst = sBase + (lr * RP + lq) * 2;
    const uint32_t bDst = aDst + 128 * RP * 2;

    const int T = K / BK;

    // prologue: stage 0
    cp_async16(aDst,      aSrc);
    cp_async16(aDst + 16, aSrc + 8);
    cp_async16(bDst,      bSrc);
    cp_async16(bDst + 16, bSrc + 8);
    cp_commit();

    const int lane = tid & 31, warp = tid >> 5;
    const int wm = warp & 1, wn = warp >> 1;   // wm: 0..1, wn: 0..3
    const int gid = lane >> 2, tq = lane & 3;

    float acc[4][4][4];
    #pragma unroll
    for (int i = 0; i < 4; i++)
        #pragma unroll
        for (int j = 0; j < 4; j++)
            #pragma unroll
            for (int r = 0; r < 4; r++) acc[i][j][r] = 0.0f;

    for (int t = 0; t < T; t++) {
        // issue loads for t+1 into the other buffer (consumed at t-1; the
        // end-of-iteration __syncthreads guarantees safety)
        if (t + 1 < T) {
            const uint32_t so = ((t + 1) & 1) * STAGE_H * 2;
            const int kt = (t + 1) * BK;
            cp_async16(aDst + so,      aSrc + kt);
            cp_async16(aDst + so + 16, aSrc + kt + 8);
            cp_async16(bDst + so,      bSrc + kt);
            cp_async16(bDst + so + 16, bSrc + kt + 8);
        }
        cp_commit();          // always commit (empty group on last iter)
        cp_wait<1>();         // stage t complete; stage t+1 in flight
        __syncthreads();

        const __half* sA = smem + (t & 1) * STAGE_H;
        const __half* sB = sA + 128 * RP;

        #pragma unroll
        for (int ks = 0; ks < 2; ks++) {
            const int k0 = ks * 16;
            uint32_t af[4][4], bf[4][2];
            #pragma unroll
            for (int i = 0; i < 4; i++) {
                const __half* pa = sA + (wm * 64 + i * 16 + gid) * RP + k0 + 2 * tq;
                af[i][0] = *(const uint32_t*)(pa);
                af[i][1] = *(const uint32_t*)(pa + 8 * RP);
                af[i][2] = *(const uint32_t*)(pa + 8);
                af[i][3] = *(const uint32_t*)(pa + 8 * RP + 8);
            }
            #pragma unroll
            for (int j = 0; j < 4; j++) {
                const __half* pb = sB + (wn * 32 + j * 8 + gid) * RP + k0 + 2 * tq;
                bf[j][0] = *(const uint32_t*)(pb);
                bf[j][1] = *(const uint32_t*)(pb + 8);
            }
            #pragma unroll
            for (int i = 0; i < 4; i++)
                #pragma unroll
                for (int j = 0; j < 4; j++)
                    mma_f16(acc[i][j], af[i], bf[j]);
        }
        __syncthreads();
    }

    // epilogue
    float2 bv[4];
    if (EPI != 0) {
        #pragma unroll
        for (int j = 0; j < 4; j++)
            bv[j] = *(const float2*)(bias + blockIdx.x * 128 + wn * 32 + j * 8 + 2 * tq);
    }
    #pragma unroll
    for (int i = 0; i < 4; i++) {
        const int row = blockIdx.y * 128 + wm * 64 + i * 16 + gid;
        #pragma unroll
        for (int j = 0; j < 4; j++) {
            const int col = blockIdx.x * 128 + wn * 32 + j * 8 + 2 * tq;
            float v0 = acc[i][j][0], v1 = acc[i][j][1];
            float v2 = acc[i][j][2], v3 = acc[i][j][3];
            if (EPI == 0) {
                v0 *= alpha; v1 *= alpha; v2 *= alpha; v3 *= alpha;
            } else if (EPI == 1) {
                v0 = gelu_exact(v0 + bv[j].x); v1 = gelu_exact(v1 + bv[j].y);
                v2 = gelu_exact(v2 + bv[j].x); v3 = gelu_exact(v3 + bv[j].y);
            } else {
                v0 += bv[j].x; v1 += bv[j].y;
                v2 += bv[j].x; v3 += bv[j].y;
            }
            if (EPI == 1) {
                __half* Ch = (__half*)Cv;
                *(__half2*)(Ch + (long long)row * ldC + col) =
                    __floats2half2_rn(v0, v1);
                *(__half2*)(Ch + (long long)(row + 8) * ldC + col) =
                    __floats2half2_rn(v2, v3);
            } else {
                float* Cf = (float*)Cv + (long long)bz * cBatch;
                *(float2*)(Cf + (long long)row * ldC + col)       = make_float2(v0, v1);
                *(float2*)(Cf + (long long)(row + 8) * ldC + col) = make_float2(v2, v3);
            }
        }
    }
}

// ============================ f32 -> f16 convert ============================
__global__ __launch_bounds__(256)
void f2h_kernel(const float* __restrict__ in, __half* __restrict__ out) {
    const size_t i = ((size_t)blockIdx.x * 256 + threadIdx.x) * 4;
    float4 v = *(const float4*)(in + i);
    *(__half2*)(out + i)     = __floats2half2_rn(v.x, v.y);
    *(__half2*)(out + i + 2) = __floats2half2_rn(v.z, v.w);
}

// ============================ transpose -> f16 ============================
__global__ __launch_bounds__(256)
void transpose_h_kernel(const float* __restrict__ in, __half* __restrict__ out,
                        int rows, int cols) {
    __shared__ float t[32][33];
    const long long boff = (long long)blockIdx.z * rows * cols;
    in += boff; out += boff;
    const int c0 = blockIdx.x * 32, r0 = blockIdx.y * 32;
    const int tx = threadIdx.x & 31, ty = threadIdx.x >> 5;  // 32 x 8
    #pragma unroll
    for (int i = 0; i < 4; i++)
        t[ty + 8 * i][tx] = in[(long long)(r0 + ty + 8 * i) * cols + c0 + tx];
    __syncthreads();
    #pragma unroll
    for (int i = 0; i < 4; i++)
        out[(long long)(c0 + ty + 8 * i) * rows + r0 + tx] =
            __float2half_rn(t[tx][ty + 8 * i]);
}

// ============================ softmax (f32 in, f16 out) ============================
__global__ __launch_bounds__(256)
void softmax_kernel(const float* __restrict__ Pin, __half* __restrict__ Pout) {
    const float* row = Pin + (size_t)blockIdx.x * 2048;
    __half* rowo = Pout + (size_t)blockIdx.x * 2048;
    const int tid = threadIdx.x;

    float4 v0 = ((const float4*)row)[tid];
    float4 v1 = ((const float4*)row)[tid + 256];

    float m = fmaxf(fmaxf(fmaxf(v0.x, v0.y), fmaxf(v0.z, v0.w)),
                    fmaxf(fmaxf(v1.x, v1.y), fmaxf(v1.z, v1.w)));

    __shared__ float smax[8];
    __shared__ float ssum[8];
    const int wid = tid >> 5, lane = tid & 31;

    #pragma unroll
    for (int o = 16; o > 0; o >>= 1)
        m = fmaxf(m, __shfl_xor_sync(0xffffffffu, m, o));
    if (lane == 0) smax[wid] = m;
    __syncthreads();
    m = smax[0];
    #pragma unroll
    for (int i = 1; i < 8; i++) m = fmaxf(m, smax[i]);

    v0.x = __expf(v0.x - m); v0.y = __expf(v0.y - m);
    v0.z = __expf(v0.z - m); v0.w = __expf(v0.w - m);
    v1.x = __expf(v1.x - m); v1.y = __expf(v1.y - m);
    v1.z = __expf(v1.z - m); v1.w = __expf(v1.w - m);

    float s = v0.x + v0.y + v0.z + v0.w + v1.x + v1.y + v1.z + v1.w;
    #pragma unroll
    for (int o = 16; o > 0; o >>= 1)
        s += __shfl_xor_sync(0xffffffffu, s, o);
    if (lane == 0) ssum[wid] = s;
    __syncthreads();
    s = ssum[0];
    #pragma unroll
    for (int i = 1; i < 8; i++) s += ssum[i];

    const float inv = 1.0f / s;
    __half2* po = (__half2*)rowo;
    po[2 * tid]           = __floats2half2_rn(v0.x * inv, v0.y * inv);
    po[2 * tid + 1]       = __floats2half2_rn(v0.z * inv, v0.w * inv);
    po[2 * (tid + 256)]     = __floats2half2_rn(v1.x * inv, v1.y * inv);
    po[2 * (tid + 256) + 1] = __floats2half2_rn(v1.z * inv, v1.w * inv);
}

// ============================ add + LayerNorm ============================
// out f32; optional f16 copy for feeding the next GEMM.
__global__ __launch_bounds__(128)
void add_ln_kernel(const float* __restrict__ A, const float* __restrict__ Bv,
                   const float* __restrict__ gamma, const float* __restrict__ beta,
                   float* __restrict__ out, __half* __restrict__ outh) {
    const size_t base = (size_t)blockIdx.x * 512;
    const int tid = threadIdx.x;

    float4 a = ((const float4*)(A + base))[tid];
    float4 b = ((const float4*)(Bv + base))[tid];
    float v0 = a.x + b.x, v1 = a.y + b.y, v2 = a.z + b.z, v3 = a.w + b.w;

    float s  = v0 + v1 + v2 + v3;
    float sq = v0 * v0 + v1 * v1 + v2 * v2 + v3 * v3;

    __shared__ float ss[4];
    __shared__ float sk[4];
    const int wid = tid >> 5, lane = tid & 31;
    #pragma unroll
    for (int o = 16; o > 0; o >>= 1) {
        s  += __shfl_xor_sync(0xffffffffu, s, o);
        sq += __shfl_xor_sync(0xffffffffu, sq, o);
    }
    if (lane == 0) { ss[wid] = s; sk[wid] = sq; }
    __syncthreads();
    s  = ss[0] + ss[1] + ss[2] + ss[3];
    sq = sk[0] + sk[1] + sk[2] + sk[3];

    const float mu  = s * (1.0f / 512.0f);
    const float var = sq * (1.0f / 512.0f) - mu * mu;
    const float rs  = rsqrtf(var + 1e-5f);

    float4 g  = ((const float4*)gamma)[tid];
    float4 be = ((const float4*)beta)[tid];

    float4 o;
    o.x = (v0 - mu) * rs * g.x + be.x;
    o.y = (v1 - mu) * rs * g.y + be.y;
    o.z = (v2 - mu) * rs * g.z + be.z;
    o.w = (v3 - mu) * rs * g.w + be.w;
    ((float4*)(out + base))[tid] = o;
    if (outh) {
        __half2* ph = (__half2*)(outh + base);
        ph[2 * tid]     = __floats2half2_rn(o.x, o.y);
        ph[2 * tid + 1] = __floats2half2_rn(o.z, o.w);
    }
}

// ============================ host ============================
extern "C" void kernel_launch(void* const* d_in, const int* in_sizes, int n_in,
                              void* d_out, int out_size) {
    const float* q     = (const float*)d_in[0];
    const float* k     = (const float*)d_in[1];
    const float* v     = (const float*)d_in[2];
    const float* ln1_g = (const float*)d_in[3];
    const float* ln1_b = (const float*)d_in[4];
    const float* w1    = (const float*)d_in[5];
    const float* b1    = (const float*)d_in[6];
    const float* w2    = (const float*)d_in[7];
    const float* b2    = (const float*)d_in[8];
    const float* ln3_g = (const float*)d_in[9];
    const float* ln3_b = (const float*)d_in[10];
    float* out = (float*)d_out;

    float *scores, *attn, *x, *ff;
    __half *ph, *xh, *hh, *qh, *kh, *vth, *w1th, *w2th;
    cudaGetSymbolAddress((void**)&scores, g_scores);
    cudaGetSymbolAddress((void**)&ph,     g_ph);
    cudaGetSymbolAddress((void**)&attn,   g_attn);
    cudaGetSymbolAddress((void**)&x,      g_x);
    cudaGetSymbolAddress((void**)&xh,     g_xh);
    cudaGetSymbolAddress((void**)&hh,     g_hh);
    cudaGetSymbolAddress((void**)&ff,     g_ff);
    cudaGetSymbolAddress((void**)&qh,     g_qh);
    cudaGetSymbolAddress((void**)&kh,     g_kh);
    cudaGetSymbolAddress((void**)&vth,    g_vth);
    cudaGetSymbolAddress((void**)&w1th,   g_w1th);
    cudaGetSymbolAddress((void**)&w2th,   g_w2th);

    cudaFuncSetAttribute(gemm_mma_kernel<0>,
                         cudaFuncAttributeMaxDynamicSharedMemorySize, GEMM_SMEM);
    cudaFuncSetAttribute(gemm_mma_kernel<1>,
                         cudaFuncAttributeMaxDynamicSharedMemorySize, GEMM_SMEM);
    cudaFuncSetAttribute(gemm_mma_kernel<2>,
                         cudaFuncAttributeMaxDynamicSharedMemorySize, GEMM_SMEM);

    const float alpha = 1.0f / sqrtf((float)EE);

    // 0) producers: f16 operand copies
    f2h_kernel<<<(size_t)NROWS * EE / 1024, 256>>>(q, qh);
    f2h_kernel<<<(size_t)NROWS * EE / 1024, 256>>>(k, kh);
    transpose_h_kernel<<<dim3(EE / 32, SS / 32, BB), 256>>>(v, vth, SS, EE);
    transpose_h_kernel<<<dim3(HH / 32, EE / 32, 1), 256>>>(w1, w1th, EE, HH);
    transpose_h_kernel<<<dim3(EE / 32, HH / 32, 1), 256>>>(w2, w2th, HH, EE);

    // 1) scores = alpha * q @ k^T   [per batch 2048x2048, K=512]
    gemm_mma_kernel<0><<<dim3(SS / 128, SS / 128, BB), 256, GEMM_SMEM>>>(
        qh, kh, scores, SS, (long long)SS * SS, SS, SS, EE, nullptr, alpha);

    // 2) softmax rows: f32 scores -> f16 P
    softmax_kernel<<<NROWS, 256>>>(scores, ph);

    // 3) attn = P @ Vt^T            [per batch 2048x512, K=2048]
    gemm_mma_kernel<0><<<dim3(EE / 128, SS / 128, BB), 256, GEMM_SMEM>>>(
        ph, vth, attn, EE, (long long)SS * EE, SS, EE, SS, nullptr, 1.0f);

    // 4) x = LN(q + attn)  (+ f16 copy)
    add_ln_kernel<<<NROWS, 128>>>(q, attn, ln1_g, ln1_b, x, xh);

    // 5) h = gelu(x @ w1t^T + b1)   [32768x1024, K=512] -> f16
    gemm_mma_kernel<1><<<dim3(HH / 128, NROWS / 128, 1), 256, GEMM_SMEM>>>(
        xh, w1th, hh, HH, 0LL, 0, 0, EE, b1, 1.0f);

    // 6) ff = h @ w2t^T + b2        [32768x512, K=1024]
    gemm_mma_kernel<2><<<dim3(EE / 128, NROWS / 128, 1), 256, GEMM_SMEM>>>(
        hh, w2th, ff, EE, 0LL, 0, 0, HH, b2, 1.0f);

    // 7) out = LN(x + ff)
    add_ln_kernel<<<NROWS, 128>>>(x, ff, ln3_g, ln3_b, out, nullptr);
}

// round 17
// speedup vs baseline: 2.8820x; 1.1427x over previous
#include <cuda_runtime.h>
#include <cuda_fp16.h>
#include <math.h>
#include <stdint.h>

// Problem shape (fixed by the reference)
#define BB 16
#define SS 2048
#define EE 512
#define HH 1024
#define NROWS (BB * SS)

// Scratch (allocation-free rule: __device__ globals)
__device__ float  g_scores[(size_t)BB * SS * SS];  // 256 MB (QK^T, f32)
__device__ __half g_ph    [(size_t)BB * SS * SS];  // 128 MB (softmax(P), f16)
__device__ float  g_attn  [(size_t)BB * SS * EE];
__device__ float  g_x     [(size_t)BB * SS * EE];
__device__ __half g_xh    [(size_t)BB * SS * EE];
__device__ __half g_hh    [(size_t)BB * SS * HH];  // gelu output, f16
__device__ float  g_ff    [(size_t)BB * SS * EE];
__device__ __half g_qh    [(size_t)BB * SS * EE];
__device__ __half g_kh    [(size_t)BB * SS * EE];
__device__ __half g_vth   [(size_t)BB * SS * EE];  // V^T per batch [E, S]
__device__ __half g_w1th  [(size_t)EE * HH];       // [H, E]
__device__ __half g_w2th  [(size_t)EE * HH];       // [E, H]

__device__ __forceinline__ float gelu_exact(float v) {
    return 0.5f * v * (1.0f + erff(v * 0.70710678118654752f));
}

// ============================ PTX helpers (base ISA only) ============================
__device__ __forceinline__ uint32_t smem_u32(const void* p) {
    uint32_t a;
    asm("{ .reg .u64 t; cvta.to.shared.u64 t, %1; cvt.u32.u64 %0, t; }"
        : "=r"(a) : "l"(p));
    return a;
}

__device__ __forceinline__ void cp_async16(uint32_t dst, const void* src) {
    asm volatile("cp.async.cg.shared.global [%0], [%1], 16;"
                 :: "r"(dst), "l"(src) : "memory");
}
__device__ __forceinline__ void cp_commit() {
    asm volatile("cp.async.commit_group;" ::: "memory");
}
template <int N>
__device__ __forceinline__ void cp_wait() {
    asm volatile("cp.async.wait_group %0;" :: "n"(N) : "memory");
}

// ldmatrix x4 on native f16 tiles (8 rows x 16B per matrix)
__device__ __forceinline__ void ldsm_x4(uint32_t* r, uint32_t addr) {
    asm volatile("ldmatrix.sync.aligned.m8n8.x4.shared.b16 {%0,%1,%2,%3}, [%4];"
                 : "=r"(r[0]), "=r"(r[1]), "=r"(r[2]), "=r"(r[3]) : "r"(addr));
}

// fp16 MMA, fp32 accumulate: D[16x8] += A[16x16] * B[8x16]^T
__device__ __forceinline__ void mma_f16(float* c, const uint32_t* a, const uint32_t* b) {
    asm volatile(
        "mma.sync.aligned.m16n8k16.row.col.f32.f16.f16.f32 "
        "{%0,%1,%2,%3}, {%4,%5,%6,%7}, {%8,%9}, {%0,%1,%2,%3};"
        : "+f"(c[0]), "+f"(c[1]), "+f"(c[2]), "+f"(c[3])
        : "r"(a[0]), "r"(a[1]), "r"(a[2]), "r"(a[3]), "r"(b[0]), "r"(b[1]));
}

// ============================ GEMM kernel ============================
// D = A @ B^T, A [*, K] row-major f16, B [*, K] row-major f16 (NT).
// CTA tile 128x128, BK=32 (halves), 2-stage cp.async pipeline (2 CTAs/SM).
// 8 warps: wm in {0,1} (64 rows), wn in {0..3} (32 cols); 2 k16-steps/chunk.
// Fragments via ldmatrix.x4 (6 loads per 16 MMAs).
// EPI: 0 = alpha*acc -> f32, 1 = bias + exact GELU -> f16, 2 = bias -> f32
#define BK 32                    // halves per K chunk
#define RP 40                    // halves per smem row (80B: ldmatrix conflict-free)
#define STAGE_H (2 * 128 * RP)   // halves per stage (A+B) = 20KB
#define GEMM_SMEM (2 * STAGE_H * 2)

template <int EPI>
__global__ __launch_bounds__(256, 2)
void gemm_mma_kernel(const __half* __restrict__ A, const __half* __restrict__ B,
                     void* __restrict__ Cv, int ldC, long long cBatch,
                     int aBatchRows, int bBatchRows, int K,
                     const float* __restrict__ bias, float alpha) {
    extern __shared__ __half smem[];
    const int tid = threadIdx.x;
    const int bz = blockIdx.z;
    const int mBase = bz * aBatchRows + blockIdx.y * 128;
    const int nBase = bz * bBatchRows + blockIdx.x * 128;

    // loader: each thread copies 2x16B for A and 2x16B for B
    const int lr = tid >> 1;            // row 0..127
    const int lq = (tid & 1) * 16;      // half offset within 32-half row
    const __half* aSrc = A + (long long)(mBase + lr) * K + lq;
    const __half* bSrc = B + (long long)(nBase + lr) * K + lq;
    const uint32_t sBase = smem_u32(smem);
    const uint32_t aDst = sBase + (lr * RP + lq) * 2;
    const uint32_t bDst = aDst + 128 * RP * 2;

    const int T = K / BK;

    // prologue: stage 0
    cp_async16(aDst,      aSrc);
    cp_async16(aDst + 16, aSrc + 8);
    cp_async16(bDst,      bSrc);
    cp_async16(bDst + 16, bSrc + 8);
    cp_commit();

    const int lane = tid & 31, warp = tid >> 5;
    const int wm = warp & 1, wn = warp >> 1;   // wm: 0..1, wn: 0..3
    const int gid = lane >> 2, tq = lane & 3;

    // ldmatrix per-lane base offsets (bytes within a stage)
    const int lm = lane >> 3, lrw = lane & 7;  // matrix id 0..3, row-in-matrix 0..7
    // A x4 (m-tile i): m0=(rows+0,k0-7) m1=(rows+8,k0-7) m2=(rows+0,k8-15) m3=(rows+8,k8-15)
    const uint32_t aOff = ((wm * 64 + (lm & 1) * 8 + lrw) * RP + (lm >> 1) * 8) * 2;
    // B x4 (pair p -> j=2p,2p+1): m0=(j,k0-7) m1=(j,k8-15) m2=(j+1,k0-7) m3=(j+1,k8-15)
    const uint32_t bOff = 128 * RP * 2 +
                          ((wn * 32 + (lm >> 1) * 8 + lrw) * RP + (lm & 1) * 8) * 2;

    float acc[4][4][4];
    #pragma unroll
    for (int i = 0; i < 4; i++)
        #pragma unroll
        for (int j = 0; j < 4; j++)
            #pragma unroll
            for (int r = 0; r < 4; r++) acc[i][j][r] = 0.0f;

    for (int t = 0; t < T; t++) {
        // issue loads for t+1 into the other buffer (consumed at t-1; the
        // end-of-iteration __syncthreads guarantees safety)
        if (t + 1 < T) {
            const uint32_t so = ((t + 1) & 1) * STAGE_H * 2;
            const int kt = (t + 1) * BK;
            cp_async16(aDst + so,      aSrc + kt);
            cp_async16(aDst + so + 16, aSrc + kt + 8);
            cp_async16(bDst + so,      bSrc + kt);
            cp_async16(bDst + so + 16, bSrc + kt + 8);
        }
        cp_commit();          // always commit (empty group on last iter)
        cp_wait<1>();         // stage t complete; stage t+1 in flight
        __syncthreads();

        const uint32_t stBase = sBase + (t & 1) * STAGE_H * 2;

        #pragma unroll
        for (int ks = 0; ks < 2; ks++) {
            const uint32_t k0b = ks * 32;      // 16 halves = 32 bytes
            uint32_t af[4][4], bf[4][2];
            #pragma unroll
            for (int i = 0; i < 4; i++)
                ldsm_x4(af[i], stBase + aOff + k0b + i * (16 * RP * 2));
            #pragma unroll
            for (int p = 0; p < 2; p++) {
                uint32_t tmp[4];
                ldsm_x4(tmp, stBase + bOff + k0b + p * (16 * RP * 2));
                bf[2 * p][0]     = tmp[0];
                bf[2 * p][1]     = tmp[1];
                bf[2 * p + 1][0] = tmp[2];
                bf[2 * p + 1][1] = tmp[3];
            }
            #pragma unroll
            for (int i = 0; i < 4; i++)
                #pragma unroll
                for (int j = 0; j < 4; j++)
                    mma_f16(acc[i][j], af[i], bf[j]);
        }
        __syncthreads();
    }

    // epilogue
    float2 bv[4];
    if (EPI != 0) {
        #pragma unroll
        for (int j = 0; j < 4; j++)
            bv[j] = *(const float2*)(bias + blockIdx.x * 128 + wn * 32 + j * 8 + 2 * tq);
    }
    #pragma unroll
    for (int i = 0; i < 4; i++) {
        const int row = blockIdx.y * 128 + wm * 64 + i * 16 + gid;
        #pragma unroll
        for (int j = 0; j < 4; j++) {
            const int col = blockIdx.x * 128 + wn * 32 + j * 8 + 2 * tq;
            float v0 = acc[i][j][0], v1 = acc[i][j][1];
            float v2 = acc[i][j][2], v3 = acc[i][j][3];
            if (EPI == 0) {
                v0 *= alpha; v1 *= alpha; v2 *= alpha; v3 *= alpha;
            } else if (EPI == 1) {
                v0 = gelu_exact(v0 + bv[j].x); v1 = gelu_exact(v1 + bv[j].y);
                v2 = gelu_exact(v2 + bv[j].x); v3 = gelu_exact(v3 + bv[j].y);
            } else {
                v0 += bv[j].x; v1 += bv[j].y;
                v2 += bv[j].x; v3 += bv[j].y;
            }
            if (EPI == 1) {
                __half* Ch = (__half*)Cv;
                *(__half2*)(Ch + (long long)row * ldC + col) =
                    __floats2half2_rn(v0, v1);
                *(__half2*)(Ch + (long long)(row + 8) * ldC + col) =
                    __floats2half2_rn(v2, v3);
            } else {
                float* Cf = (float*)Cv + (long long)bz * cBatch;
                *(float2*)(Cf + (long long)row * ldC + col)       = make_float2(v0, v1);
                *(float2*)(Cf + (long long)(row + 8) * ldC + col) = make_float2(v2, v3);
            }
        }
    }
}

// ============================ f32 -> f16 convert ============================
__global__ __launch_bounds__(256)
void f2h_kernel(const float* __restrict__ in, __half* __restrict__ out) {
    const size_t i = ((size_t)blockIdx.x * 256 + threadIdx.x) * 4;
    float4 v = *(const float4*)(in + i);
    *(__half2*)(out + i)     = __floats2half2_rn(v.x, v.y);
    *(__half2*)(out + i + 2) = __floats2half2_rn(v.z, v.w);
}

// ============================ transpose -> f16 ============================
__global__ __launch_bounds__(256)
void transpose_h_kernel(const float* __restrict__ in, __half* __restrict__ out,
                        int rows, int cols) {
    __shared__ float t[32][33];
    const long long boff = (long long)blockIdx.z * rows * cols;
    in += boff; out += boff;
    const int c0 = blockIdx.x * 32, r0 = blockIdx.y * 32;
    const int tx = threadIdx.x & 31, ty = threadIdx.x >> 5;  // 32 x 8
    #pragma unroll
    for (int i = 0; i < 4; i++)
        t[ty + 8 * i][tx] = in[(long long)(r0 + ty + 8 * i) * cols + c0 + tx];
    __syncthreads();
    #pragma unroll
    for (int i = 0; i < 4; i++)
        out[(long long)(c0 + ty + 8 * i) * rows + r0 + tx] =
            __float2half_rn(t[tx][ty + 8 * i]);
}

// ============================ softmax (f32 in, f16 out) ============================
__global__ __launch_bounds__(256)
void softmax_kernel(const float* __restrict__ Pin, __half* __restrict__ Pout) {
    const float* row = Pin + (size_t)blockIdx.x * 2048;
    __half* rowo = Pout + (size_t)blockIdx.x * 2048;
    const int tid = threadIdx.x;

    float4 v0 = ((const float4*)row)[tid];
    float4 v1 = ((const float4*)row)[tid + 256];

    float m = fmaxf(fmaxf(fmaxf(v0.x, v0.y), fmaxf(v0.z, v0.w)),
                    fmaxf(fmaxf(v1.x, v1.y), fmaxf(v1.z, v1.w)));

    __shared__ float smax[8];
    __shared__ float ssum[8];
    const int wid = tid >> 5, lane = tid & 31;

    #pragma unroll
    for (int o = 16; o > 0; o >>= 1)
        m = fmaxf(m, __shfl_xor_sync(0xffffffffu, m, o));
    if (lane == 0) smax[wid] = m;
    __syncthreads();
    m = smax[0];
    #pragma unroll
    for (int i = 1; i < 8; i++) m = fmaxf(m, smax[i]);

    v0.x = __expf(v0.x - m); v0.y = __expf(v0.y - m);
    v0.z = __expf(v0.z - m); v0.w = __expf(v0.w - m);
    v1.x = __expf(v1.x - m); v1.y = __expf(v1.y - m);
    v1.z = __expf(v1.z - m); v1.w = __expf(v1.w - m);

    float s = v0.x + v0.y + v0.z + v0.w + v1.x + v1.y + v1.z + v1.w;
    #pragma unroll
    for (int o = 16; o > 0; o >>= 1)
        s += __shfl_xor_sync(0xffffffffu, s, o);
    if (lane == 0) ssum[wid] = s;
    __syncthreads();
    s = ssum[0];
    #pragma unroll
    for (int i = 1; i < 8; i++) s += ssum[i];

    const float inv = 1.0f / s;
    __half2* po = (__half2*)rowo;
    po[2 * tid]           = __floats2half2_rn(v0.x * inv, v0.y * inv);
    po[2 * tid + 1]       = __floats2half2_rn(v0.z * inv, v0.w * inv);
    po[2 * (tid + 256)]     = __floats2half2_rn(v1.x * inv, v1.y * inv);
    po[2 * (tid + 256) + 1] = __floats2half2_rn(v1.z * inv, v1.w * inv);
}

// ============================ add + LayerNorm ============================
// out f32; optional f16 copy for feeding the next GEMM.
__global__ __launch_bounds__(128)
void add_ln_kernel(const float* __restrict__ A, const float* __restrict__ Bv,
                   const float* __restrict__ gamma, const float* __restrict__ beta,
                   float* __restrict__ out, __half* __restrict__ outh) {
    const size_t base = (size_t)blockIdx.x * 512;
    const int tid = threadIdx.x;

    float4 a = ((const float4*)(A + base))[tid];
    float4 b = ((const float4*)(Bv + base))[tid];
    float v0 = a.x + b.x, v1 = a.y + b.y, v2 = a.z + b.z, v3 = a.w + b.w;

    float s  = v0 + v1 + v2 + v3;
    float sq = v0 * v0 + v1 * v1 + v2 * v2 + v3 * v3;

    __shared__ float ss[4];
    __shared__ float sk[4];
    const int wid = tid >> 5, lane = tid & 31;
    #pragma unroll
    for (int o = 16; o > 0; o >>= 1) {
        s  += __shfl_xor_sync(0xffffffffu, s, o);
        sq += __shfl_xor_sync(0xffffffffu, sq, o);
    }
    if (lane == 0) { ss[wid] = s; sk[wid] = sq; }
    __syncthreads();
    s  = ss[0] + ss[1] + ss[2] + ss[3];
    sq = sk[0] + sk[1] + sk[2] + sk[3];

    const float mu  = s * (1.0f / 512.0f);
    const float var = sq * (1.0f / 512.0f) - mu * mu;
    const float rs  = rsqrtf(var + 1e-5f);

    float4 g  = ((const float4*)gamma)[tid];
    float4 be = ((const float4*)beta)[tid];

    float4 o;
    o.x = (v0 - mu) * rs * g.x + be.x;
    o.y = (v1 - mu) * rs * g.y + be.y;
    o.z = (v2 - mu) * rs * g.z + be.z;
    o.w = (v3 - mu) * rs * g.w + be.w;
    ((float4*)(out + base))[tid] = o;
    if (outh) {
        __half2* ph = (__half2*)(outh + base);
        ph[2 * tid]     = __floats2half2_rn(o.x, o.y);
        ph[2 * tid + 1] = __floats2half2_rn(o.z, o.w);
    }
}

// ============================ host ============================
extern "C" void kernel_launch(void* const* d_in, const int* in_sizes, int n_in,
                              void* d_out, int out_size) {
    const float* q     = (const float*)d_in[0];
    const float* k     = (const float*)d_in[1];
    const float* v     = (const float*)d_in[2];
    const float* ln1_g = (const float*)d_in[3];
    const float* ln1_b = (const float*)d_in[4];
    const float* w1    = (const float*)d_in[5];
    const float* b1    = (const float*)d_in[6];
    const float* w2    = (const float*)d_in[7];
    const float* b2    = (const float*)d_in[8];
    const float* ln3_g = (const float*)d_in[9];
    const float* ln3_b = (const float*)d_in[10];
    float* out = (float*)d_out;

    float *scores, *attn, *x, *ff;
    __half *ph, *xh, *hh, *qh, *kh, *vth, *w1th, *w2th;
    cudaGetSymbolAddress((void**)&scores, g_scores);
    cudaGetSymbolAddress((void**)&ph,     g_ph);
    cudaGetSymbolAddress((void**)&attn,   g_attn);
    cudaGetSymbolAddress((void**)&x,      g_x);
    cudaGetSymbolAddress((void**)&xh,     g_xh);
    cudaGetSymbolAddress((void**)&hh,     g_hh);
    cudaGetSymbolAddress((void**)&ff,     g_ff);
    cudaGetSymbolAddress((void**)&qh,     g_qh);
    cudaGetSymbolAddress((void**)&kh,     g_kh);
    cudaGetSymbolAddress((void**)&vth,    g_vth);
    cudaGetSymbolAddress((void**)&w1th,   g_w1th);
    cudaGetSymbolAddress((void**)&w2th,   g_w2th);

    cudaFuncSetAttribute(gemm_mma_kernel<0>,
                         cudaFuncAttributeMaxDynamicSharedMemorySize, GEMM_SMEM);
    cudaFuncSetAttribute(gemm_mma_kernel<1>,
                         cudaFuncAttributeMaxDynamicSharedMemorySize, GEMM_SMEM);
    cudaFuncSetAttribute(gemm_mma_kernel<2>,
                         cudaFuncAttributeMaxDynamicSharedMemorySize, GEMM_SMEM);

    const float alpha = 1.0f / sqrtf((float)EE);

    // 0) producers: f16 operand copies
    f2h_kernel<<<(size_t)NROWS * EE / 1024, 256>>>(q, qh);
    f2h_kernel<<<(size_t)NROWS * EE / 1024, 256>>>(k, kh);
    transpose_h_kernel<<<dim3(EE / 32, SS / 32, BB), 256>>>(v, vth, SS, EE);
    transpose_h_kernel<<<dim3(HH / 32, EE / 32, 1), 256>>>(w1, w1th, EE, HH);
    transpose_h_kernel<<<dim3(EE / 32, HH / 32, 1), 256>>>(w2, w2th, HH, EE);

    // 1) scores = alpha * q @ k^T   [per batch 2048x2048, K=512]
    gemm_mma_kernel<0><<<dim3(SS / 128, SS / 128, BB), 256, GEMM_SMEM>>>(
        qh, kh, scores, SS, (long long)SS * SS, SS, SS, EE, nullptr, alpha);

    // 2) softmax rows: f32 scores -> f16 P
    softmax_kernel<<<NROWS, 256>>>(scores, ph);

    // 3) attn = P @ Vt^T            [per batch 2048x512, K=2048]
    gemm_mma_kernel<0><<<dim3(EE / 128, SS / 128, BB), 256, GEMM_SMEM>>>(
        ph, vth, attn, EE, (long long)SS * EE, SS, EE, SS, nullptr, 1.0f);

    // 4) x = LN(q + attn)  (+ f16 copy)
    add_ln_kernel<<<NROWS, 128>>>(q, attn, ln1_g, ln1_b, x, xh);

    // 5) h = gelu(x @ w1t^T + b1)   [32768x1024, K=512] -> f16
    gemm_mma_kernel<1><<<dim3(HH / 128, NROWS / 128, 1), 256, GEMM_SMEM>>>(
        xh, w1th, hh, HH, 0LL, 0, 0, EE, b1, 1.0f);

    // 6) ff = h @ w2t^T + b2        [32768x512, K=1024]
    gemm_mma_kernel<2><<<dim3(EE / 128, NROWS / 128, 1), 256, GEMM_SMEM>>>(
        hh, w2th, ff, EE, 0LL, 0, 0, HH, b2, 1.0f);

    // 7) out = LN(x + ff)
    add_ln_kernel<<<NROWS, 128>>>(x, ff, ln3_g, ln3_b, out, nullptr);
}